// round 1
// baseline (speedup 1.0000x reference)
#include <cuda_runtime.h>
#include <math.h>
#include <stdint.h>

#define DD   768
#define NH   12
#define HD   64
#define NB   8
#define LL   1024
#define NEGV (-1000000.0f)

// ---------------- scratch (device globals; no cudaMalloc allowed) -------------
__device__ float g_Q[NB * LL * DD];
__device__ float g_K[NB * LL * DD];
__device__ float g_V[NB * LL * DD];
__device__ float g_S[(size_t)NB * NH * LL * LL];   // 402 MB scores/attn
__device__ float g_attn[NB * LL * DD];
__device__ float g_mha[NB * LL * DD];
__device__ float g_h1[NB * LL * DD];
__device__ float g_x[NB * LL * DD];
__device__ int   g_vl[2][NB];

// ---------------- mask valid-length counts ------------------------------------
__global__ void count_masks_kernel(const int* __restrict__ m1,
                                   const int* __restrict__ m2) {
    const int* m = (blockIdx.y == 0) ? m1 : m2;
    int b = blockIdx.x;
    int t = threadIdx.x;
    __shared__ int red[256];
    int cnt = 0;
    for (int i = t; i < LL; i += 256) cnt += (m[b * LL + i] != 0);
    red[t] = cnt;
    __syncthreads();
    for (int s = 128; s > 0; s >>= 1) {
        if (t < s) red[t] += red[t + s];
        __syncthreads();
    }
    if (t == 0) g_vl[blockIdx.y][b] = red[0];
}

// ---------------- generic NN SGEMM: C[M,N] = A[M,K] @ B[K,N] ------------------
// 128x128 tile, BK=8, 256 threads, 8x8 per-thread micro-tile.
// flags: 1=+bias[col], 2=relu, 4=+resid[r*N+c]
__global__ void __launch_bounds__(256)
sgemm_nn_kernel(const float* __restrict__ A, const float* __restrict__ Bm,
                const float* __restrict__ bias, const float* __restrict__ resid,
                float* __restrict__ C, int M, int N, int K, int flags) {
    __shared__ float As[8][128];
    __shared__ float Bs[8][128];
    const int t  = threadIdx.x;
    const int bm = blockIdx.y * 128;
    const int bn = blockIdx.x * 128;
    const int tr = t >> 4;   // 0..15
    const int tc = t & 15;   // 0..15

    float acc[8][8];
#pragma unroll
    for (int i = 0; i < 8; ++i)
#pragma unroll
        for (int j = 0; j < 8; ++j) acc[i][j] = 0.0f;

    const int arow = t >> 1, ac4 = t & 1;     // A tile: 128 rows x 8 cols
    const int brow = t >> 5, bc4 = t & 31;    // B tile: 8 rows x 128 cols

    for (int k0 = 0; k0 < K; k0 += 8) {
        float4 va = *(const float4*)&A[(size_t)(bm + arow) * K + k0 + ac4 * 4];
        As[ac4 * 4 + 0][arow] = va.x;
        As[ac4 * 4 + 1][arow] = va.y;
        As[ac4 * 4 + 2][arow] = va.z;
        As[ac4 * 4 + 3][arow] = va.w;
        float4 vb = *(const float4*)&Bm[(size_t)(k0 + brow) * N + bn + bc4 * 4];
        *(float4*)&Bs[brow][bc4 * 4] = vb;
        __syncthreads();
#pragma unroll
        for (int k = 0; k < 8; ++k) {
            float a[8], bv[8];
            *(float4*)&a[0]  = *(const float4*)&As[k][tr * 8];
            *(float4*)&a[4]  = *(const float4*)&As[k][tr * 8 + 4];
            *(float4*)&bv[0] = *(const float4*)&Bs[k][tc * 8];
            *(float4*)&bv[4] = *(const float4*)&Bs[k][tc * 8 + 4];
#pragma unroll
            for (int i = 0; i < 8; ++i)
#pragma unroll
                for (int j = 0; j < 8; ++j) acc[i][j] += a[i] * bv[j];
        }
        __syncthreads();
    }

#pragma unroll
    for (int i = 0; i < 8; ++i) {
        int r = bm + tr * 8 + i;
#pragma unroll
        for (int j = 0; j < 8; ++j) {
            int c = bn + tc * 8 + j;
            float v = acc[i][j];
            if (flags & 1) v += bias[c];
            if (flags & 2) v = fmaxf(v, 0.0f);
            if (flags & 4) v += resid[(size_t)r * N + c];
            C[(size_t)r * N + c] = v;
        }
    }
}

// ---------------- batched scores: S[bh,i,j] = (Qh[i,:] . Kh[j,:]) / 8, masked --
__global__ void __launch_bounds__(256)
scores_kernel(const float* __restrict__ Q, const float* __restrict__ Kk,
              float* __restrict__ S) {
    const int bh = blockIdx.z;
    const int b  = bh / NH;
    const int h  = bh % NH;
    const float* A  = Q  + (size_t)b * LL * DD + h * HD;
    const float* Bm = Kk + (size_t)b * LL * DD + h * HD;
    float* C = S + (size_t)bh * LL * LL;

    __shared__ float As[8][128];
    __shared__ float Bs[8][128];
    const int t  = threadIdx.x;
    const int bm = blockIdx.y * 128;   // query rows
    const int bn = blockIdx.x * 128;   // key rows
    const int tr = t >> 4;
    const int tc = t & 15;

    float acc[8][8];
#pragma unroll
    for (int i = 0; i < 8; ++i)
#pragma unroll
        for (int j = 0; j < 8; ++j) acc[i][j] = 0.0f;

    const int row = t >> 1, c4 = t & 1;   // both tiles: 128 rows x 8 cols (of hd)

    for (int k0 = 0; k0 < HD; k0 += 8) {
        float4 va = *(const float4*)&A[(size_t)(bm + row) * DD + k0 + c4 * 4];
        As[c4 * 4 + 0][row] = va.x;
        As[c4 * 4 + 1][row] = va.y;
        As[c4 * 4 + 2][row] = va.z;
        As[c4 * 4 + 3][row] = va.w;
        float4 vb = *(const float4*)&Bm[(size_t)(bn + row) * DD + k0 + c4 * 4];
        Bs[c4 * 4 + 0][row] = vb.x;
        Bs[c4 * 4 + 1][row] = vb.y;
        Bs[c4 * 4 + 2][row] = vb.z;
        Bs[c4 * 4 + 3][row] = vb.w;
        __syncthreads();
#pragma unroll
        for (int k = 0; k < 8; ++k) {
            float a[8], bv[8];
            *(float4*)&a[0]  = *(const float4*)&As[k][tr * 8];
            *(float4*)&a[4]  = *(const float4*)&As[k][tr * 8 + 4];
            *(float4*)&bv[0] = *(const float4*)&Bs[k][tc * 8];
            *(float4*)&bv[4] = *(const float4*)&Bs[k][tc * 8 + 4];
#pragma unroll
            for (int i = 0; i < 8; ++i)
#pragma unroll
                for (int j = 0; j < 8; ++j) acc[i][j] += a[i] * bv[j];
        }
        __syncthreads();
    }

    const int vl1 = g_vl[0][b];   // key-axis valid length
    const int vl2 = g_vl[1][b];   // query-axis valid length
#pragma unroll
    for (int i = 0; i < 8; ++i) {
        int r = bm + tr * 8 + i;
        bool rok = r < vl2;
#pragma unroll
        for (int j = 0; j < 8; ++j) {
            int c = bn + tc * 8 + j;
            float v = acc[i][j] * 0.125f;
            C[(size_t)r * LL + c] = (rok && c < vl1) ? v : NEGV;
        }
    }
}

// ---------------- row softmax over 1024 ---------------------------------------
__global__ void __launch_bounds__(256) softmax_kernel(float* __restrict__ S) {
    const size_t row = blockIdx.x;
    float* p = S + row * LL;
    const int t = threadIdx.x;
    __shared__ float red[256];
    __shared__ float bcast;

    float4 v = *(const float4*)&p[t * 4];
    float m = fmaxf(fmaxf(v.x, v.y), fmaxf(v.z, v.w));
    red[t] = m;
    __syncthreads();
    for (int s = 128; s > 0; s >>= 1) {
        if (t < s) red[t] = fmaxf(red[t], red[t + s]);
        __syncthreads();
    }
    if (t == 0) bcast = red[0];
    __syncthreads();
    float mx = bcast;

    float4 e;
    e.x = __expf(v.x - mx);
    e.y = __expf(v.y - mx);
    e.z = __expf(v.z - mx);
    e.w = __expf(v.w - mx);
    red[t] = e.x + e.y + e.z + e.w;
    __syncthreads();
    for (int s = 128; s > 0; s >>= 1) {
        if (t < s) red[t] += red[t + s];
        __syncthreads();
    }
    if (t == 0) bcast = red[0];
    __syncthreads();
    float inv = 1.0f / bcast;

    e.x *= inv; e.y *= inv; e.z *= inv; e.w *= inv;
    *(float4*)&p[t * 4] = e;
}

// ---------------- batched PV: O[bh] = P[1024,1024] @ Vh[1024,64] --------------
// 128x64 tile, BK=16, 256 threads, 8x4 per-thread.
__global__ void __launch_bounds__(256)
pv_kernel(const float* __restrict__ S, const float* __restrict__ V,
          float* __restrict__ O) {
    const int bh = blockIdx.z;
    const int b  = bh / NH;
    const int h  = bh % NH;
    const float* A  = S + (size_t)bh * LL * LL;
    const float* Bm = V + (size_t)b * LL * DD + h * HD;
    float* C = O + (size_t)b * LL * DD + h * HD;

    __shared__ float As[16][128];
    __shared__ float Bs[16][64];
    const int t  = threadIdx.x;
    const int bm = blockIdx.y * 128;
    const int tr = t >> 4;   // 0..15 -> 8 rows each
    const int tc = t & 15;   // 0..15 -> 4 cols each

    float acc[8][4];
#pragma unroll
    for (int i = 0; i < 8; ++i)
#pragma unroll
        for (int j = 0; j < 4; ++j) acc[i][j] = 0.0f;

    const int brow = t >> 4, bc4 = t & 15;  // B tile: 16 rows x 64 cols

    for (int k0 = 0; k0 < LL; k0 += 16) {
        // A tile: 128 rows x 16 cols = 512 float4, 2 per thread
#pragma unroll
        for (int g = 0; g < 2; ++g) {
            int gi  = t * 2 + g;
            int row = gi >> 2, c4 = gi & 3;
            float4 va = *(const float4*)&A[(size_t)(bm + row) * LL + k0 + c4 * 4];
            As[c4 * 4 + 0][row] = va.x;
            As[c4 * 4 + 1][row] = va.y;
            As[c4 * 4 + 2][row] = va.z;
            As[c4 * 4 + 3][row] = va.w;
        }
        float4 vb = *(const float4*)&Bm[(size_t)(k0 + brow) * DD + bc4 * 4];
        *(float4*)&Bs[brow][bc4 * 4] = vb;
        __syncthreads();
#pragma unroll
        for (int k = 0; k < 16; ++k) {
            float a[8], bv[4];
            *(float4*)&a[0]  = *(const float4*)&As[k][tr * 8];
            *(float4*)&a[4]  = *(const float4*)&As[k][tr * 8 + 4];
            *(float4*)&bv[0] = *(const float4*)&Bs[k][tc * 4];
#pragma unroll
            for (int i = 0; i < 8; ++i)
#pragma unroll
                for (int j = 0; j < 4; ++j) acc[i][j] += a[i] * bv[j];
        }
        __syncthreads();
    }

#pragma unroll
    for (int i = 0; i < 8; ++i) {
        int r = bm + tr * 8 + i;
#pragma unroll
        for (int j = 0; j < 4; ++j)
            C[(size_t)r * DD + tc * 4 + j] = acc[i][j];
    }
}

// ---------------- layernorm over D=768 ----------------------------------------
__global__ void __launch_bounds__(256)
ln_kernel(const float* __restrict__ X, const float* __restrict__ gam,
          const float* __restrict__ bet, float* __restrict__ out) {
    const size_t row = blockIdx.x;
    const float* x = X + row * DD;
    const int t = threadIdx.x;
    __shared__ float red[256];
    __shared__ float bcast;

    float v0 = x[t], v1 = x[t + 256], v2 = x[t + 512];
    red[t] = v0 + v1 + v2;
    __syncthreads();
    for (int s = 128; s > 0; s >>= 1) {
        if (t < s) red[t] += red[t + s];
        __syncthreads();
    }
    if (t == 0) bcast = red[0] * (1.0f / DD);
    __syncthreads();
    float mu = bcast;

    float d0 = v0 - mu, d1 = v1 - mu, d2 = v2 - mu;
    red[t] = d0 * d0 + d1 * d1 + d2 * d2;
    __syncthreads();
    for (int s = 128; s > 0; s >>= 1) {
        if (t < s) red[t] += red[t + s];
        __syncthreads();
    }
    if (t == 0) bcast = red[0] * (1.0f / DD);
    __syncthreads();
    float inv = rsqrtf(bcast + 1e-5f);

    out[row * DD + t]       = d0 * inv * gam[t]       + bet[t];
    out[row * DD + t + 256] = d1 * inv * gam[t + 256] + bet[t + 256];
    out[row * DD + t + 512] = d2 * inv * gam[t + 512] + bet[t + 512];
}

// ---------------- launch --------------------------------------------------------
extern "C" void kernel_launch(void* const* d_in, const int* in_sizes, int n_in,
                              void* d_out, int out_size) {
    const float* queries = (const float*)d_in[0];
    const float* keys    = (const float*)d_in[1];
    const float* values  = (const float*)d_in[2];
    const int*   mask_1  = (const int*)  d_in[3];
    const int*   mask_2  = (const int*)  d_in[4];
    const float* Wq      = (const float*)d_in[5];
    const float* Wk      = (const float*)d_in[6];
    const float* Wv      = (const float*)d_in[7];
    const float* Wo      = (const float*)d_in[8];
    const float* d1_w    = (const float*)d_in[9];
    const float* d1_b    = (const float*)d_in[10];
    const float* d2_w    = (const float*)d_in[11];
    const float* d2_b    = (const float*)d_in[12];
    const float* ln_g    = (const float*)d_in[13];
    const float* ln_b    = (const float*)d_in[14];
    float* out = (float*)d_out;

    float *Qd, *Kd, *Vd, *Sd, *Ad, *Md, *H1, *Xd;
    cudaGetSymbolAddress((void**)&Qd, g_Q);
    cudaGetSymbolAddress((void**)&Kd, g_K);
    cudaGetSymbolAddress((void**)&Vd, g_V);
    cudaGetSymbolAddress((void**)&Sd, g_S);
    cudaGetSymbolAddress((void**)&Ad, g_attn);
    cudaGetSymbolAddress((void**)&Md, g_mha);
    cudaGetSymbolAddress((void**)&H1, g_h1);
    cudaGetSymbolAddress((void**)&Xd, g_x);

    const int M = NB * LL;           // 8192
    dim3 gProj(DD / 128, M / 128);   // (6, 64)

    count_masks_kernel<<<dim3(NB, 2), 256>>>(mask_1, mask_2);

    sgemm_nn_kernel<<<gProj, 256>>>(queries, Wq, nullptr, nullptr, Qd, M, DD, DD, 0);
    sgemm_nn_kernel<<<gProj, 256>>>(keys,    Wk, nullptr, nullptr, Kd, M, DD, DD, 0);
    sgemm_nn_kernel<<<gProj, 256>>>(values,  Wv, nullptr, nullptr, Vd, M, DD, DD, 0);

    scores_kernel<<<dim3(LL / 128, LL / 128, NB * NH), 256>>>(Qd, Kd, Sd);
    softmax_kernel<<<NB * NH * LL, 256>>>(Sd);
    pv_kernel<<<dim3(1, LL / 128, NB * NH), 256>>>(Sd, Vd, Ad);

    sgemm_nn_kernel<<<gProj, 256>>>(Ad, Wo,   nullptr, nullptr, Md, M, DD, DD, 0);
    sgemm_nn_kernel<<<gProj, 256>>>(Md, d1_w, d1_b,    nullptr, H1, M, DD, DD, 1 | 2);
    sgemm_nn_kernel<<<gProj, 256>>>(H1, d2_w, d2_b,    Md,      Xd, M, DD, DD, 1 | 4);

    ln_kernel<<<M, 256>>>(Xd, ln_g, ln_b, out);
}